// round 10
// baseline (speedup 1.0000x reference)
#include <cuda_runtime.h>
#include <cuda_bf16.h>

// Problem constants
#define LSEQ       103
#define V4_STRIDE  33                   // float4 row stride for s_d4/s_p4 (bank spread)
#define DNA_ELEMS  (32 * 4 * LSEQ)      // 13184 floats, contiguous per CTA
#define PROT_ELEMS (8 * 21 * LSEQ)      // 17304 floats, contiguous per group (8 batches)
#define DNA_V4     (DNA_ELEMS / 4)      // 3296
#define PROT_V4    (PROT_ELEMS / 4)     // 4326
#define SLAB_BYTES (PROT_V4 * 16)       // 69216 B dynamic smem

__global__ __launch_bounds__(256, 2)
void ma_block_kernel(const float* __restrict__ dna,
                     const float* __restrict__ prot,
                     const float* __restrict__ w_dna,
                     const float* __restrict__ w_prot,
                     const float* __restrict__ w_lin,
                     const float* __restrict__ b_lin,
                     float* __restrict__ out)
{
    extern __shared__ float4 s_slab4[];          // contiguous slab: dna block / prot groups
    __shared__ float4 s_d4[32 * V4_STRIDE];      // d triples: [k][m] = {d[3m],d[3m+1],d[3m+2],0}
    __shared__ float4 s_p4[32 * V4_STRIDE];      // p triples, same layout
    __shared__ float  s_wd[32];                  // (4,8)
    __shared__ float  s_wp[168];                 // (21,8)
    __shared__ float  s_wl[192];                 // (2,96)
    __shared__ float  s_bl[2];

    float* s_slab = reinterpret_cast<float*>(s_slab4);

    const int tid = threadIdx.x;
    const int u   = blockIdx.x;                  // 0..1023

    if (tid < 32)  s_wd[tid] = w_dna[tid];
    if (tid < 168) s_wp[tid] = w_prot[tid];
    if (tid < 192) s_wl[tid] = w_lin[tid];
    if (tid < 2)   s_bl[tid] = b_lin[tid];

    // ---------------- DNA: contiguous float4 copy, then conv ----------------
    {
        const float4* src = reinterpret_cast<const float4*>(dna + (size_t)u * DNA_ELEMS);
        #pragma unroll
        for (int i = tid; i < DNA_V4; i += 256)
            s_slab4[i] = src[i];
        __syncthreads();

        // thread: one batch-row, 12 consecutive conv outputs (m = 4*seg .. 4*seg+3)
        const int row = tid >> 3;                // 0..31 (batch)
        const int seg = tid & 7;
        const int j0  = seg * 12;

        float acc[12];
        #pragma unroll
        for (int jj = 0; jj < 12; jj++) acc[jj] = 0.f;

        #pragma unroll
        for (int r = 0; r < 4; r++) {
            const float* srow = s_slab + (row * 4 + r) * LSEQ + j0;
            float win[19];
            #pragma unroll
            for (int x = 0; x < 19; x++) win[x] = srow[x];
            #pragma unroll
            for (int k = 0; k < 8; k++) {
                const float w = s_wd[r * 8 + k];
                #pragma unroll
                for (int jj = 0; jj < 12; jj++)
                    acc[jj] = fmaf(win[jj + k], w, acc[jj]);
            }
        }
        #pragma unroll
        for (int mi = 0; mi < 4; mi++)
            s_d4[row * V4_STRIDE + seg * 4 + mi] =
                make_float4(fmaxf(acc[3*mi+0], 0.f), fmaxf(acc[3*mi+1], 0.f),
                            fmaxf(acc[3*mi+2], 0.f), 0.f);
    }

    // ---------------- PROT: 4 groups of 8 batches ----------------
    // warp = batch-in-group; lane: rq = lane>>3 (row-quarter), seg = lane&7 (12 cols).
    // rq0 handles rows 0..5, rq k>=1 rows 5k+1..5k+5; partials combined via shuffles.
    {
        const int b    = tid >> 5;               // 0..7 batch in group (== warp)
        const int lane = tid & 31;
        const int rq   = lane >> 3;              // 0..3
        const int seg  = lane & 7;               // 0..7
        const int j0   = seg * 12;
        const int nrows = (rq == 0) ? 6 : 5;
        const int rbase = (rq == 0) ? 0 : (5 * rq + 1);

        for (int g = 0; g < 4; g++) {
            __syncthreads();                     // prior slab readers done
            const float4* src = reinterpret_cast<const float4*>(
                prot + (size_t)u * (32 * 21 * LSEQ) + (size_t)g * PROT_ELEMS);
            #pragma unroll
            for (int i = tid; i < PROT_V4; i += 256)
                s_slab4[i] = src[i];
            __syncthreads();

            float acc[12];
            #pragma unroll
            for (int jj = 0; jj < 12; jj++) acc[jj] = 0.f;

            #pragma unroll
            for (int i = 0; i < 6; i++) {
                if (i < nrows) {
                    const int r = rbase + i;
                    const float* srow = s_slab + (b * 21 + r) * LSEQ + j0;
                    float win[19];
                    #pragma unroll
                    for (int x = 0; x < 19; x++) win[x] = srow[x];
                    #pragma unroll
                    for (int k = 0; k < 8; k++) {
                        const float w = s_wp[r * 8 + k];
                        #pragma unroll
                        for (int jj = 0; jj < 12; jj++)
                            acc[jj] = fmaf(win[jj + k], w, acc[jj]);
                    }
                }
            }

            // combine the 4 row-quarter partials (butterfly over lane bits 3,4)
            #pragma unroll
            for (int jj = 0; jj < 12; jj++) {
                acc[jj] += __shfl_xor_sync(0xffffffffu, acc[jj], 8);
                acc[jj] += __shfl_xor_sync(0xffffffffu, acc[jj], 16);
            }
            if (lane < 8) {
                const int krow = (g * 8 + b) * V4_STRIDE + seg * 4;
                #pragma unroll
                for (int mi = 0; mi < 4; mi++)
                    s_p4[krow + mi] =
                        make_float4(fmaxf(acc[3*mi+0], 0.f), fmaxf(acc[3*mi+1], 0.f),
                                    fmaxf(acc[3*mi+2], 0.f), 0.f);
            }
        }
    }

    __syncthreads();

    // ---------------- attention + linear (single fused pass, no max-sub) ----------------
    // Output b' = 1024*m + u: query = s_p4[lane][m], keys/values = s_d4[k][m].
    // softmax(lg*scale) computed without max subtraction: |lg*scale| << 88, no overflow.
    const int warp = tid >> 5;
    const int lane = tid & 31;

    // hoist per-lane linear weights (j = 3*lane)
    const int jl = lane * 3;
    const float wl00 = s_wl[jl],      wl01 = s_wl[jl + 1],      wl02 = s_wl[jl + 2];
    const float wl10 = s_wl[96 + jl], wl11 = s_wl[96 + jl + 1], wl12 = s_wl[96 + jl + 2];

    #pragma unroll 1
    for (int mi = 0; mi < 4; mi++) {
        const int m = warp * 4 + mi;             // 0..31

        const float4 qv = s_p4[lane * V4_STRIDE + m];
        const float scale = 0.5773502691896258f; // 1/sqrt(3)
        const float q0 = qv.x * scale, q1 = qv.y * scale, q2 = qv.z * scale;

        float sum = 0.f, o0 = 0.f, o1 = 0.f, o2 = 0.f;
        #pragma unroll
        for (int k = 0; k < 32; k++) {
            const float4 v = s_d4[k * V4_STRIDE + m];   // broadcast LDS.128
            const float l = q0 * v.x + q1 * v.y + q2 * v.z;
            const float e = __expf(l);
            sum += e;
            o0 = fmaf(e, v.x, o0);
            o1 = fmaf(e, v.y, o1);
            o2 = fmaf(e, v.z, o2);
        }
        const float inv = 1.f / sum;
        o0 *= inv; o1 *= inv; o2 *= inv;

        float p0 = o0 * wl00 + o1 * wl01 + o2 * wl02;
        float p1 = o0 * wl10 + o1 * wl11 + o2 * wl12;

        #pragma unroll
        for (int off = 16; off > 0; off >>= 1) {
            p0 += __shfl_xor_sync(0xffffffffu, p0, off);
            p1 += __shfl_xor_sync(0xffffffffu, p1, off);
        }
        if (lane == 0) {
            const int b2 = m * 1024 + u;
            out[b2 * 2 + 0] = p0 + s_bl[0];
            out[b2 * 2 + 1] = p1 + s_bl[1];
        }
    }
}

extern "C" void kernel_launch(void* const* d_in, const int* in_sizes, int n_in,
                              void* d_out, int out_size)
{
    const float* dna    = (const float*)d_in[0];   // (32768,1,4,103)
    const float* prot   = (const float*)d_in[1];   // (32768,1,21,103)
    const float* w_dna  = (const float*)d_in[2];   // (1,1,4,8)
    const float* w_prot = (const float*)d_in[3];   // (1,1,21,8)
    const float* w_lin  = (const float*)d_in[4];   // (2,96)
    const float* b_lin  = (const float*)d_in[5];   // (2,)
    float* out = (float*)d_out;                    // (32768,1,2)

    cudaFuncSetAttribute(ma_block_kernel,
                         cudaFuncAttributeMaxDynamicSharedMemorySize,
                         (int)SLAB_BYTES);

    ma_block_kernel<<<1024, 256, SLAB_BYTES>>>(dna, prot, w_dna, w_prot, w_lin, b_lin, out);
}

// round 12
// speedup vs baseline: 1.1622x; 1.1622x over previous
#include <cuda_runtime.h>
#include <cuda_bf16.h>
#include <cstdint>

// Problem constants
#define LSEQ       103
#define V4_STRIDE  33                    // float4 row stride for s_d4/s_p4
#define DNA_H4     1648                  // float4 per dna half (16 batches * 4 * 103 / 4)
#define PROT_G4    2163                  // float4 per prot group (4 batches * 21 * 103 / 4)
#define BUF4       PROT_G4               // buffer size in float4 (max chunk)
#define SLAB_BYTES (2 * BUF4 * 16)       // 69216 B dynamic smem (2 buffers)

__device__ __forceinline__ void cp16(uint32_t dst, const void* src) {
    asm volatile("cp.async.cg.shared.global [%0], [%1], 16;" :: "r"(dst), "l"(src));
}

__global__ __launch_bounds__(256, 2)
void ma_block_kernel(const float* __restrict__ dna,
                     const float* __restrict__ prot,
                     const float* __restrict__ w_dna,
                     const float* __restrict__ w_prot,
                     const float* __restrict__ w_lin,
                     const float* __restrict__ b_lin,
                     float* __restrict__ out)
{
    extern __shared__ float4 s_buf4[];           // [2][BUF4] double buffer
    __shared__ float4 s_d4[32 * V4_STRIDE];      // d triples: [k][m] = {d[3m],d[3m+1],d[3m+2],0}
    __shared__ float4 s_p4[32 * V4_STRIDE];      // p triples, same layout
    __shared__ float  s_wd[32];                  // (4,8)
    __shared__ float  s_wp[168];                 // (21,8)
    __shared__ float  s_wl[192];                 // (2,96)
    __shared__ float  s_bl[2];

    const int tid = threadIdx.x;
    const int u   = blockIdx.x;                  // 0..1023

    if (tid < 32)  s_wd[tid] = w_dna[tid];
    if (tid < 168) s_wp[tid] = w_prot[tid];
    if (tid < 192) s_wl[tid] = w_lin[tid];
    if (tid < 2)   s_bl[tid] = b_lin[tid];

    const float4* dna4  = reinterpret_cast<const float4*>(dna  + (size_t)u * (32 * 4  * LSEQ));
    const float4* prot4 = reinterpret_cast<const float4*>(prot + (size_t)u * (32 * 21 * LSEQ));
    const uint32_t sbase = (uint32_t)__cvta_generic_to_shared(s_buf4);

    // Issue async copy of chunk c into buffer bsel.
    // Chunks: 0,1 = dna halves (16 batches each); 2..9 = prot groups (4 batches each).
    auto issue = [&](int c, int bsel) {
        const uint32_t ba = sbase + (uint32_t)bsel * (BUF4 * 16);
        if (c < 2) {
            const float4* src = dna4 + c * DNA_H4;
            for (int i = tid; i < DNA_H4; i += 256)
                cp16(ba + i * 16, src + i);
        } else {
            const float4* src = prot4 + (c - 2) * PROT_G4;
            for (int i = tid; i < PROT_G4; i += 256)
                cp16(ba + i * 16, src + i);
        }
        asm volatile("cp.async.commit_group;" ::: "memory");
    };

    // ---- conv on one dna half (16 batches): thread = (row16, seg), 6 outputs ----
    auto compute_dna = [&](int hd, const float* buf) {
        const int row16 = tid >> 4;              // 0..15 local batch
        const int seg   = tid & 15;              // 0..15
        const int j0    = seg * 6;               // 0..90

        float acc[6];
        #pragma unroll
        for (int jj = 0; jj < 6; jj++) acc[jj] = 0.f;

        #pragma unroll
        for (int r = 0; r < 4; r++) {
            const float* srow = buf + (row16 * 4 + r) * LSEQ + j0;
            float win[13];
            #pragma unroll
            for (int x = 0; x < 13; x++) win[x] = srow[x];
            #pragma unroll
            for (int k = 0; k < 8; k++) {
                const float w = s_wd[r * 8 + k];
                #pragma unroll
                for (int jj = 0; jj < 6; jj++)
                    acc[jj] = fmaf(win[jj + k], w, acc[jj]);
            }
        }
        const int kk = hd * 16 + row16;
        s_d4[kk * V4_STRIDE + seg * 2 + 0] =
            make_float4(fmaxf(acc[0], 0.f), fmaxf(acc[1], 0.f), fmaxf(acc[2], 0.f), 0.f);
        s_d4[kk * V4_STRIDE + seg * 2 + 1] =
            make_float4(fmaxf(acc[3], 0.f), fmaxf(acc[4], 0.f), fmaxf(acc[5], 0.f), 0.f);
    };

    // ---- conv on one prot group (4 batches): warp = (batch, col-half), 6 outputs ----
    auto compute_prot = [&](int g, const float* buf) {
        const int warp    = tid >> 5;            // 0..7
        const int b_local = warp >> 1;           // 0..3
        const int h       = warp & 1;            // col half
        const int lane    = tid & 31;
        const int rq      = lane >> 3;           // 0..3 row-quarter
        const int seg     = lane & 7;            // 0..7
        const int j0      = h * 48 + seg * 6;    // 0..90
        const int nrows   = (rq == 0) ? 6 : 5;
        const int rbase   = (rq == 0) ? 0 : (5 * rq + 1);

        float acc[6];
        #pragma unroll
        for (int jj = 0; jj < 6; jj++) acc[jj] = 0.f;

        #pragma unroll
        for (int i = 0; i < 6; i++) {
            if (i < nrows) {
                const int r = rbase + i;
                const float* srow = buf + (b_local * 21 + r) * LSEQ + j0;
                float win[13];
                #pragma unroll
                for (int x = 0; x < 13; x++) win[x] = srow[x];
                #pragma unroll
                for (int k = 0; k < 8; k++) {
                    const float w = s_wp[r * 8 + k];
                    #pragma unroll
                    for (int jj = 0; jj < 6; jj++)
                        acc[jj] = fmaf(win[jj + k], w, acc[jj]);
                }
            }
        }
        #pragma unroll
        for (int jj = 0; jj < 6; jj++) {
            acc[jj] += __shfl_xor_sync(0xffffffffu, acc[jj], 8);
            acc[jj] += __shfl_xor_sync(0xffffffffu, acc[jj], 16);
        }
        if (lane < 8) {
            const int kk   = g * 4 + b_local;
            const int base = kk * V4_STRIDE + h * 16 + seg * 2;
            s_p4[base + 0] =
                make_float4(fmaxf(acc[0], 0.f), fmaxf(acc[1], 0.f), fmaxf(acc[2], 0.f), 0.f);
            s_p4[base + 1] =
                make_float4(fmaxf(acc[3], 0.f), fmaxf(acc[4], 0.f), fmaxf(acc[5], 0.f), 0.f);
        }
    };

    // ---------------- double-buffered pipeline over 10 chunks ----------------
    issue(0, 0);
    issue(1, 1);
    #pragma unroll 1
    for (int c = 0; c < 10; c++) {
        if (c < 9) asm volatile("cp.async.wait_group 1;" ::: "memory");
        else       asm volatile("cp.async.wait_group 0;" ::: "memory");
        __syncthreads();                         // chunk c visible to all threads
        const float* buf = reinterpret_cast<const float*>(s_buf4 + (c & 1) * BUF4);
        if (c < 2) compute_dna(c, buf);
        else       compute_prot(c - 2, buf);
        __syncthreads();                         // all readers of buf done
        if (c + 2 < 10) issue(c + 2, c & 1);     // overlaps with next iteration's compute
    }

    // ---------------- attention + linear (single fused pass, no max-sub) ----------------
    // Output b' = 1024*m + u: query = s_p4[lane][m], keys/values = s_d4[k][m].
    // softmax(lg*scale) without max subtraction: |lg*scale| << 88, no overflow possible.
    const int warp = tid >> 5;
    const int lane = tid & 31;

    const int jl = lane * 3;
    const float wl00 = s_wl[jl],      wl01 = s_wl[jl + 1],      wl02 = s_wl[jl + 2];
    const float wl10 = s_wl[96 + jl], wl11 = s_wl[96 + jl + 1], wl12 = s_wl[96 + jl + 2];

    #pragma unroll 1
    for (int mi = 0; mi < 4; mi++) {
        const int m = warp * 4 + mi;             // 0..31

        const float4 qv = s_p4[lane * V4_STRIDE + m];
        const float scale = 0.5773502691896258f; // 1/sqrt(3)
        const float q0 = qv.x * scale, q1 = qv.y * scale, q2 = qv.z * scale;

        float sum = 0.f, o0 = 0.f, o1 = 0.f, o2 = 0.f;
        #pragma unroll
        for (int k = 0; k < 32; k++) {
            const float4 v = s_d4[k * V4_STRIDE + m];   // broadcast LDS.128
            const float l = q0 * v.x + q1 * v.y + q2 * v.z;
            const float e = __expf(l);
            sum += e;
            o0 = fmaf(e, v.x, o0);
            o1 = fmaf(e, v.y, o1);
            o2 = fmaf(e, v.z, o2);
        }
        const float inv = 1.f / sum;
        o0 *= inv; o1 *= inv; o2 *= inv;

        float p0 = o0 * wl00 + o1 * wl01 + o2 * wl02;
        float p1 = o0 * wl10 + o1 * wl11 + o2 * wl12;

        #pragma unroll
        for (int off = 16; off > 0; off >>= 1) {
            p0 += __shfl_xor_sync(0xffffffffu, p0, off);
            p1 += __shfl_xor_sync(0xffffffffu, p1, off);
        }
        if (lane == 0) {
            const int b2 = m * 1024 + u;
            out[b2 * 2 + 0] = p0 + s_bl[0];
            out[b2 * 2 + 1] = p1 + s_bl[1];
        }
    }
}

extern "C" void kernel_launch(void* const* d_in, const int* in_sizes, int n_in,
                              void* d_out, int out_size)
{
    const float* dna    = (const float*)d_in[0];   // (32768,1,4,103)
    const float* prot   = (const float*)d_in[1];   // (32768,1,21,103)
    const float* w_dna  = (const float*)d_in[2];   // (1,1,4,8)
    const float* w_prot = (const float*)d_in[3];   // (1,1,21,8)
    const float* w_lin  = (const float*)d_in[4];   // (2,96)
    const float* b_lin  = (const float*)d_in[5];   // (2,)
    float* out = (float*)d_out;                    // (32768,1,2)

    cudaFuncSetAttribute(ma_block_kernel,
                         cudaFuncAttributeMaxDynamicSharedMemorySize,
                         (int)SLAB_BYTES);

    ma_block_kernel<<<1024, 256, SLAB_BYTES>>>(dna, prot, w_dna, w_prot, w_lin, b_lin, out);
}